// round 14
// baseline (speedup 1.0000x reference)
#include <cuda_runtime.h>
#include <cuda_bf16.h>
#include <cstdint>

static constexpr int N   = 256;
static constexpr int B   = 512;
static constexpr int M   = N * (N - 1) / 2;   // 32640
static constexpr int TPB = 128;               // 4 warps; warp owns 32 batches
static constexpr int SS  = 36;                // smem row stride: 16B-aligned + conflict-free
static constexpr int WBUF = 32 * SS;          // floats per warp buffer
static constexpr long long NN = (long long)N * N;

__device__ __forceinline__ float sqrt_approx(float x) {
    float r;
    asm("sqrt.approx.f32 %0, %1;" : "=f"(r) : "f"(x));
    return r;
}

// Reference step; x2 = fma(-z2, rs, z2) = z2*(1-rs) in one rounding. Identical
// to the reference wherever rs >= 0.5 (Sterbenz: 1-rs exact), which covers the
// deep-column plateau; <= 1 ulp relative difference below. Chain: 8 cyc/elem.
__device__ __forceinline__ float chol_step(float z, float& rs) {
    float z2 = __fmul_rn(z, z);
    float x2 = __fmaf_rn(-z2, rs, z2);
    rs       = __fadd_rn(rs, x2);
    return copysignf(sqrt_approx(x2), z);
}

__device__ __forceinline__ uint32_t su32(const void* p) {
    return (uint32_t)__cvta_generic_to_shared(p);
}
// 4B async copy: copies szb (0 or 4) bytes, zero-fills the rest of 4.
__device__ __forceinline__ void cp4(uint32_t dst, const float* src, int szb) {
    asm volatile("cp.async.ca.shared.global [%0], [%1], 4, %2;\n"
                 :: "r"(dst), "l"(src), "r"(szb));
}
#define CP_COMMIT() asm volatile("cp.async.commit_group;\n")
#define CP_WAIT(nn) asm volatile("cp.async.wait_group %0;\n" :: "n"(nn) : "memory")

// Load one 32-column tile for 32 batch streams into this warp's buffer.
// Per k: lanes read consecutive input columns -> coalesced 128B LDGSTS.
__device__ __forceinline__ void cp_tile(float* __restrict__ buf,
                                        const float* __restrict__ vbase,
                                        int i, int j0, int lane) {
    const int j  = j0 + lane;
    const int ok = (j < i);
    const int sz = ok ? 4 : 0;
    const float* src0 = vbase + (ok ? j : 0);
    #pragma unroll
    for (int k = 0; k < 32; ++k)
        cp4(su32(&buf[k * SS + lane]), src0 + (size_t)k * M, sz);
}

__global__ void __launch_bounds__(TPB, 5)
chol_from_z_kernel(const float* __restrict__ vec, float* __restrict__ out) {
    __shared__ float sw[2 * 4 * WBUF];        // 36.9 KB: double-buffered warp slices

    const int i    = (N - 1) - (int)blockIdx.x;   // longest rows first
    const int wrp  = (int)threadIdx.x >> 5;
    const int lane = (int)threadIdx.x & 31;
    const int bw   = (int)blockIdx.y * TPB + wrp * 32;  // warp's batch base
    const int tri  = (i * (i - 1)) >> 1;

    const float* __restrict__ vbase = vec + (size_t)bw * M + tri;
    float* __restrict__ obase = out + ((size_t)bw * N + i) * (size_t)N;
    float* __restrict__ s0 = sw + (2 * wrp + 0) * WBUF;
    float* __restrict__ s1 = sw + (2 * wrp + 1) * WBUF;

    const int ntiles = (i >> 5) + 1;          // last tile is mixed

    // ---- prologue: async-load tile 0 ----
    cp_tile(s0, vbase, i, 0, lane);
    CP_COMMIT();

    float rs = 0.0f;
    for (int t = 0; t < ntiles; ++t) {
        const int j0 = t << 5;
        float* __restrict__ s = (t & 1) ? s1 : s0;

        // ---- prefetch tile t+1 into the other buffer, then wait for tile t ----
        if (t + 1 < ntiles) {
            cp_tile((t & 1) ? s0 : s1, vbase, i, j0 + 32, lane);
            CP_COMMIT();
            CP_WAIT(1);                       // tile t done; t+1 stays in flight
        } else {
            CP_WAIT(0);
        }
        __syncwarp();                         // cross-lane visibility of cp data

        // ---- compute: lane = batch, serial chain over 32 columns ----
        {
            float v[32];
            #pragma unroll
            for (int q = 0; q < 8; ++q) {     // LDS.128: aligned (SS=36), clean banks
                float4 f = *reinterpret_cast<const float4*>(&s[lane * SS + 4 * q]);
                v[4*q] = f.x; v[4*q+1] = f.y; v[4*q+2] = f.z; v[4*q+3] = f.w;
            }
            if (j0 + 32 <= i) {               // full tile
                #pragma unroll
                for (int jj = 0; jj < 32; ++jj) v[jj] = chol_step(v[jj], rs);
            } else {                          // mixed: scan tail, diag 1, zeros
                #pragma unroll
                for (int jj = 0; jj < 32; ++jj) {
                    int j = j0 + jj;          // uniform across warp
                    if (j < i)  v[jj] = chol_step(v[jj], rs);
                    else        v[jj] = (j == i) ? 1.0f : 0.0f;
                }
            }
            #pragma unroll
            for (int q = 0; q < 8; ++q)       // in-place writeback
                *reinterpret_cast<float4*>(&s[lane * SS + 4 * q]) =
                    make_float4(v[4*q], v[4*q+1], v[4*q+2], v[4*q+3]);
        }
        __syncwarp();                         // store phase reads other lanes' rows

        // ---- store tile: LDS.128 conflict-free, STG.128 (4x128B lines/op) ----
        #pragma unroll
        for (int st = 0; st < 8; ++st) {
            int flat = lane + 32 * st;        // 256 quads: (batch k, quad q)
            int k = flat >> 3, q = flat & 7;
            float4 f = *reinterpret_cast<const float4*>(&s[k * SS + 4 * q]);
            *reinterpret_cast<float4*>(&obase[(size_t)k * NN + j0 + 4 * q]) = f;
        }
        // No sync needed: warp-uniform program order keeps these LDS ahead of
        // the next iteration's cp.async writes into this buffer.
    }

    // ---- pure-zero region: columns [32*ntiles, N), aligned float4 stores ----
    const int zs = ntiles << 5;
    if (zs < N) {
        const int nzq = (N - zs) >> 2;
        const float4 z4 = make_float4(0.f, 0.f, 0.f, 0.f);
        for (int k = 0; k < 32; ++k) {
            float4* o4 = reinterpret_cast<float4*>(&obase[(size_t)k * NN + zs]);
            for (int q = lane; q < nzq; q += 32)
                o4[q] = z4;
        }
    }
}

extern "C" void kernel_launch(void* const* d_in, const int* in_sizes, int n_in,
                              void* d_out, int out_size) {
    const float* vec = (const float*)d_in[0];
    float* out = (float*)d_out;
    dim3 grid(N, B / TPB);                    // (256, 4) -> 1024 blocks, 4096 warps
    chol_from_z_kernel<<<grid, TPB>>>(vec, out);
}